// round 5
// baseline (speedup 1.0000x reference)
#include <cuda_runtime.h>

#define D   16
#define LIB 969
#define TPB 256
#define RPT 2
#define ROWS_PER_BLOCK (RPT * TPB)   // 512

// First 8 floats of each coeff row live in constant memory (read via LDC,
// dedicated constant port); last 8 floats live in global, staged to smem
// (read via broadcast LDS.128, LSU path). This splits load traffic across
// two independent ports so only the fma pipe is near saturation.
__constant__ float c_half[LIB * 8];   // 31008 B
__device__   float g_half[LIB * 8];

// packed fp32x2 FMA: acc = m * c + acc
#define FFMA2(acc, m, c) \
    asm("fma.rn.f32x2 %0, %1, %2, %0;" : "+l"(acc) : "l"(m), "l"(c))
// packed fp32x2 MUL
#define MULX2(dst, a, b) \
    asm("mul.rn.f32x2 %0, %1, %2;" : "=l"(dst) : "l"(a), "l"(b))
// unpack b64 -> two u32
#define UNPK(lo, hi, p) \
    asm("mov.b64 {%0, %1}, %2;" : "=r"(lo), "=r"(hi) : "l"(p))
// splat u32 -> b64
#define SPLAT(dst, s) \
    asm("mov.b64 %0, {%1, %1};" : "=l"(dst) : "r"(s))

__device__ __forceinline__ ulonglong2 ldc_v2(unsigned long long caddr) {
    ulonglong2 r;
    asm("ld.const.v2.u64 {%0, %1}, [%2];" : "=l"(r.x), "=l"(r.y) : "l"(caddr));
    return r;
}

__global__ void prep_kernel(const float* __restrict__ coeff,
                            const float* __restrict__ fixedv,
                            const unsigned char* __restrict__ fmask,
                            float* __restrict__ cdst)   // c_half backing store
{
    int i = blockIdx.x * blockDim.x + threadIdx.x;     // i = row*16 + col
    if (i < LIB * D) {
        float v = fmask[i] ? fixedv[i] : coeff[i];
        int row = i >> 4, col = i & 15;
        if (col < 8) cdst[row * 8 + col] = v;
        else         g_half[row * 8 + (col - 8)] = v;
    }
}

__global__ __launch_bounds__(TPB, 3) void sindy_kernel(
    const float* __restrict__ z,
    float* __restrict__ out,
    int B)
{
    extern __shared__ char smem[];
    float* scf = (float*)smem;                               // LIB*8 floats
    unsigned long long* zs =
        (unsigned long long*)(smem + LIB * 8 * sizeof(float)); // [D][TPB] packed

    const int tid = threadIdx.x;

    // Stage the smem half of the coefficients
    for (int i = tid; i < LIB * 8; i += TPB) scf[i] = g_half[i];

    unsigned long long cbase;
    asm("mov.u64 %0, c_half;" : "=l"(cbase));

    const long r0 = (long)blockIdx.x * ROWS_PER_BLOCK + tid;
    const long r1 = r0 + TPB;
    const bool v0 = r0 < B, v1 = r1 < B;

    // Load 2 z rows, zero-fill invalid, pack pairs into smem [k][tid]
    {
        const float4* p0 = (const float4*)(z + r0 * D);
        const float4* p1 = (const float4*)(z + r1 * D);
#pragma unroll
        for (int q = 0; q < 4; q++) {
            float4 t0 = v0 ? p0[q] : make_float4(0.f,0.f,0.f,0.f);
            float4 t1 = v1 ? p1[q] : make_float4(0.f,0.f,0.f,0.f);
            float a[4] = {t0.x,t0.y,t0.z,t0.w};
            float b[4] = {t1.x,t1.y,t1.z,t1.w};
#pragma unroll
            for (int s = 0; s < 4; s++) {
                unsigned long long p;
                asm("mov.b64 %0, {%1, %2};" : "=l"(p)
                    : "r"(__float_as_uint(a[s])), "r"(__float_as_uint(b[s])));
                zs[(4*q+s) * TPB + tid] = p;
            }
        }
    }
    __syncthreads();

    // Accumulators: 4 packed (cols 0..7) from const half, 4 packed (cols 8..15)
    // from smem half. Init = constant-term row (theta col 0 == 1).
    unsigned long long aA[8], aB[8];
    const ulonglong2* cps = (const ulonglong2*)scf;   // smem half stream
    {
        ulonglong2 i0 = ldc_v2(cbase + 0);
        ulonglong2 i1 = ldc_v2(cbase + 16);
        ulonglong2 s0 = cps[0];
        ulonglong2 s1 = cps[1];
        aA[0]=i0.x; aA[1]=i0.y; aA[2]=i1.x; aA[3]=i1.y;
        aA[4]=s0.x; aA[5]=s0.y; aA[6]=s1.x; aA[7]=s1.y;
#pragma unroll
        for (int p = 0; p < 8; p++) aB[p] = aA[p];
    }
    cps += 2;
    unsigned long long cptr = cbase + 32;

    // Software-pipelined constant-half prefetch (row 1)
    ulonglong2 p0 = ldc_v2(cptr), p1 = ldc_v2(cptr + 16);
    cptr += 32;

    // One coeff row: prefetch next const half, LDS current smem half, 16 FFMA2
#define ROW(mp) do {                                                        \
        ulonglong2 n0 = ldc_v2(cptr);                                       \
        ulonglong2 n1 = ldc_v2(cptr + 16);                                  \
        cptr += 32;                                                         \
        ulonglong2 s0 = cps[0];                                             \
        ulonglong2 s1 = cps[1];                                             \
        cps += 2;                                                           \
        unsigned uA_, uB_; unsigned long long sA_, sB_;                     \
        UNPK(uA_, uB_, (mp)); SPLAT(sA_, uA_); SPLAT(sB_, uB_);             \
        FFMA2(aA[0], sA_, p0.x); FFMA2(aB[0], sB_, p0.x);                   \
        FFMA2(aA[1], sA_, p0.y); FFMA2(aB[1], sB_, p0.y);                   \
        FFMA2(aA[2], sA_, p1.x); FFMA2(aB[2], sB_, p1.x);                   \
        FFMA2(aA[3], sA_, p1.y); FFMA2(aB[3], sB_, p1.y);                   \
        FFMA2(aA[4], sA_, s0.x); FFMA2(aB[4], sB_, s0.x);                   \
        FFMA2(aA[5], sA_, s0.y); FFMA2(aB[5], sB_, s0.y);                   \
        FFMA2(aA[6], sA_, s1.x); FFMA2(aB[6], sB_, s1.x);                   \
        FFMA2(aA[7], sA_, s1.y); FFMA2(aB[7], sB_, s1.y);                   \
        p0 = n0; p1 = n1;                                                   \
    } while (0)

    // ---- order 1: z_i ----
#pragma unroll 1
    for (int i = 0; i < D; i++) {
        unsigned long long mp = zs[i * TPB + tid];
        ROW(mp);
    }
    // ---- order 2: z_i * z_j, i<=j ----
#pragma unroll 1
    for (int i = 0; i < D; i++) {
        unsigned long long zi = zs[i * TPB + tid];
#pragma unroll 1
        for (int j = i; j < D; j++) {
            unsigned long long mp;
            MULX2(mp, zi, zs[j * TPB + tid]);
            ROW(mp);
        }
    }
    // ---- order 3: z_i * z_j * z_k, i<=j<=k ----
#pragma unroll 1
    for (int i = 0; i < D; i++) {
        unsigned long long zi = zs[i * TPB + tid];
#pragma unroll 1
        for (int j = i; j < D; j++) {
            unsigned long long pp;
            MULX2(pp, zi, zs[j * TPB + tid]);
#pragma unroll 1
            for (int k = j; k < D; k++) {
                unsigned long long mp;
                MULX2(mp, pp, zs[k * TPB + tid]);
                ROW(mp);
            }
        }
    }
#undef ROW

    if (v0) {
        ulonglong2* o = (ulonglong2*)(out + r0 * D);
        o[0] = make_ulonglong2(aA[0], aA[1]); o[1] = make_ulonglong2(aA[2], aA[3]);
        o[2] = make_ulonglong2(aA[4], aA[5]); o[3] = make_ulonglong2(aA[6], aA[7]);
    }
    if (v1) {
        ulonglong2* o = (ulonglong2*)(out + r1 * D);
        o[0] = make_ulonglong2(aB[0], aB[1]); o[1] = make_ulonglong2(aB[2], aB[3]);
        o[2] = make_ulonglong2(aB[4], aB[5]); o[3] = make_ulonglong2(aB[6], aB[7]);
    }
}

extern "C" void kernel_launch(void* const* d_in, const int* in_sizes, int n_in,
                              void* d_out, int out_size)
{
    const float*         z      = (const float*)d_in[0];
    const float*         coeff  = (const float*)d_in[1];
    const float*         fixedv = (const float*)d_in[2];
    const unsigned char* fmask  = (const unsigned char*)d_in[3];
    float*               out    = (float*)d_out;

    const int B = in_sizes[0] / D;

    void* csym = nullptr;
    cudaGetSymbolAddress(&csym, c_half);

    prep_kernel<<<(LIB * D + 255) / 256, 256>>>(coeff, fixedv, fmask,
                                                (float*)csym);

    const int smem_bytes = LIB * 8 * (int)sizeof(float)
                         + D * TPB * (int)sizeof(unsigned long long); // 63776 B
    cudaFuncSetAttribute(sindy_kernel,
                         cudaFuncAttributeMaxDynamicSharedMemorySize, smem_bytes);

    const int grid = (B + ROWS_PER_BLOCK - 1) / ROWS_PER_BLOCK;
    sindy_kernel<<<grid, TPB, smem_bytes>>>(z, out, B);
}

// round 7
// speedup vs baseline: 1.0896x; 1.0896x over previous
#include <cuda_runtime.h>

#define D   16
#define LIB 969
#define TPB 256
#define RPT 2
#define ROWS_PER_BLOCK (RPT * TPB)   // 512

// Coefficient split: cols 0..7 of each row in constant memory (LDC, dedicated
// constant port), cols 8..15 staged to smem (broadcast LDS.128, crossbar).
// Each port runs at <50% so only the fma pipe is near saturation.
__constant__ float c_half[LIB * 8];   // 31008 B
__device__   float g_half[LIB * 8];

// packed fp32x2 FMA: acc = m * c + acc
#define FFMA2(acc, m, c) \
    asm("fma.rn.f32x2 %0, %1, %2, %0;" : "+l"(acc) : "l"(m), "l"(c))
// packed fp32x2 MUL
#define MULX2(dst, a, b) \
    asm("mul.rn.f32x2 %0, %1, %2;" : "=l"(dst) : "l"(a), "l"(b))
// unpack b64 -> two u32
#define UNPK(lo, hi, p) \
    asm("mov.b64 {%0, %1}, %2;" : "=r"(lo), "=r"(hi) : "l"(p))
// splat u32 -> b64
#define SPLAT(dst, s) \
    asm("mov.b64 %0, {%1, %1};" : "=l"(dst) : "r"(s))

__device__ __forceinline__ ulonglong2 ldc_v2(unsigned long long caddr) {
    ulonglong2 r;
    asm("ld.const.v2.u64 {%0, %1}, [%2];" : "=l"(r.x), "=l"(r.y) : "l"(caddr));
    return r;
}

__global__ void prep_kernel(const float* __restrict__ coeff,
                            const float* __restrict__ fixedv,
                            const unsigned char* __restrict__ fmask,
                            float* __restrict__ cdst)   // c_half backing store
{
    int i = blockIdx.x * blockDim.x + threadIdx.x;      // i = row*16 + col
    if (i < LIB * D) {
        float v = fmask[i] ? fixedv[i] : coeff[i];
        int row = i >> 4, col = i & 15;
        if (col < 8) cdst[row * 8 + col] = v;
        else         g_half[row * 8 + (col - 8)] = v;
    }
}

__global__ __launch_bounds__(TPB, 3) void sindy_kernel(
    const float* __restrict__ z,
    float* __restrict__ out,
    int B)
{
    extern __shared__ char smem[];
    float* scf = (float*)smem;                                   // LIB*8 floats
    unsigned long long* zs =
        (unsigned long long*)(smem + LIB * 8 * sizeof(float));   // [D][TPB]

    const int tid = threadIdx.x;

    // Stage the smem half of the coefficients
    for (int i = tid; i < LIB * 8; i += TPB) scf[i] = g_half[i];

    unsigned long long cbase;
    asm("mov.u64 %0, c_half;" : "=l"(cbase));

    const long r0 = (long)blockIdx.x * ROWS_PER_BLOCK + tid;
    const long r1 = r0 + TPB;
    const bool v0 = r0 < B, v1 = r1 < B;

    // Load 2 z rows, zero-fill invalid, pack pairs into smem [k][tid]
    {
        const float4* p0 = (const float4*)(z + r0 * D);
        const float4* p1 = (const float4*)(z + r1 * D);
#pragma unroll
        for (int q = 0; q < 4; q++) {
            float4 t0 = v0 ? p0[q] : make_float4(0.f,0.f,0.f,0.f);
            float4 t1 = v1 ? p1[q] : make_float4(0.f,0.f,0.f,0.f);
            float a[4] = {t0.x,t0.y,t0.z,t0.w};
            float b[4] = {t1.x,t1.y,t1.z,t1.w};
#pragma unroll
            for (int s = 0; s < 4; s++) {
                unsigned long long p;
                asm("mov.b64 %0, {%1, %2};" : "=l"(p)
                    : "r"(__float_as_uint(a[s])), "r"(__float_as_uint(b[s])));
                zs[(4*q+s) * TPB + tid] = p;
            }
        }
    }
    __syncthreads();

    // Accumulators: [0..3] const half (cols 0..7), [4..7] smem half (cols 8..15)
    unsigned long long aA[8], aB[8];
    const ulonglong2* cps = (const ulonglong2*)scf;
    {
        ulonglong2 i0 = ldc_v2(cbase + 0);
        ulonglong2 i1 = ldc_v2(cbase + 16);
        ulonglong2 s0 = cps[0];
        ulonglong2 s1 = cps[1];
        aA[0]=i0.x; aA[1]=i0.y; aA[2]=i1.x; aA[3]=i1.y;
        aA[4]=s0.x; aA[5]=s0.y; aA[6]=s1.x; aA[7]=s1.y;
#pragma unroll
        for (int p = 0; p < 8; p++) aB[p] = aA[p];
    }
    cps += 2;
    unsigned long long cptr = cbase + 32;

    // One coeff row: 2 LDC.128 + 2 LDS.128 + splat + 16 FFMA2.
    // No explicit prefetch registers — unroll-2 below gives ptxas a 2-row
    // window to hoist loads and hide LDC/LDS latency without extra MOVs.
#define ROW(mp) do {                                                        \
        ulonglong2 q0 = ldc_v2(cptr);                                       \
        ulonglong2 q1 = ldc_v2(cptr + 16);                                  \
        cptr += 32;                                                         \
        ulonglong2 s0 = cps[0];                                             \
        ulonglong2 s1 = cps[1];                                             \
        cps += 2;                                                           \
        unsigned uA_, uB_; unsigned long long sA_, sB_;                     \
        UNPK(uA_, uB_, (mp)); SPLAT(sA_, uA_); SPLAT(sB_, uB_);             \
        FFMA2(aA[0], sA_, q0.x); FFMA2(aB[0], sB_, q0.x);                   \
        FFMA2(aA[1], sA_, q0.y); FFMA2(aB[1], sB_, q0.y);                   \
        FFMA2(aA[2], sA_, q1.x); FFMA2(aB[2], sB_, q1.x);                   \
        FFMA2(aA[3], sA_, q1.y); FFMA2(aB[3], sB_, q1.y);                   \
        FFMA2(aA[4], sA_, s0.x); FFMA2(aB[4], sB_, s0.x);                   \
        FFMA2(aA[5], sA_, s0.y); FFMA2(aB[5], sB_, s0.y);                   \
        FFMA2(aA[6], sA_, s1.x); FFMA2(aB[6], sB_, s1.x);                   \
        FFMA2(aA[7], sA_, s1.y); FFMA2(aB[7], sB_, s1.y);                   \
    } while (0)

    // ---- order 1: z_i ----
#pragma unroll 2
    for (int i = 0; i < D; i++) {
        unsigned long long mp = zs[i * TPB + tid];
        ROW(mp);
    }
    // ---- order 2: z_i * z_j, i<=j ----
#pragma unroll 1
    for (int i = 0; i < D; i++) {
        unsigned long long zi = zs[i * TPB + tid];
#pragma unroll 2
        for (int j = i; j < D; j++) {
            unsigned long long mp;
            MULX2(mp, zi, zs[j * TPB + tid]);
            ROW(mp);
        }
    }
    // ---- order 3: z_i * z_j * z_k, i<=j<=k ----
#pragma unroll 1
    for (int i = 0; i < D; i++) {
        unsigned long long zi = zs[i * TPB + tid];
#pragma unroll 1
        for (int j = i; j < D; j++) {
            unsigned long long pp;
            MULX2(pp, zi, zs[j * TPB + tid]);
#pragma unroll 2
            for (int k = j; k < D; k++) {
                unsigned long long mp;
                MULX2(mp, pp, zs[k * TPB + tid]);
                ROW(mp);
            }
        }
    }
#undef ROW

    if (v0) {
        ulonglong2* o = (ulonglong2*)(out + r0 * D);
        o[0] = make_ulonglong2(aA[0], aA[1]); o[1] = make_ulonglong2(aA[2], aA[3]);
        o[2] = make_ulonglong2(aA[4], aA[5]); o[3] = make_ulonglong2(aA[6], aA[7]);
    }
    if (v1) {
        ulonglong2* o = (ulonglong2*)(out + r1 * D);
        o[0] = make_ulonglong2(aB[0], aB[1]); o[1] = make_ulonglong2(aB[2], aB[3]);
        o[2] = make_ulonglong2(aB[4], aB[5]); o[3] = make_ulonglong2(aB[6], aB[7]);
    }
}

extern "C" void kernel_launch(void* const* d_in, const int* in_sizes, int n_in,
                              void* d_out, int out_size)
{
    const float*         z      = (const float*)d_in[0];
    const float*         coeff  = (const float*)d_in[1];
    const float*         fixedv = (const float*)d_in[2];
    const unsigned char* fmask  = (const unsigned char*)d_in[3];
    float*               out    = (float*)d_out;

    const int B = in_sizes[0] / D;

    void* csym = nullptr;
    cudaGetSymbolAddress(&csym, c_half);

    prep_kernel<<<(LIB * D + 255) / 256, 256>>>(coeff, fixedv, fmask,
                                                (float*)csym);

    const int smem_bytes = LIB * 8 * (int)sizeof(float)
                         + D * TPB * (int)sizeof(unsigned long long); // 63776 B
    cudaFuncSetAttribute(sindy_kernel,
                         cudaFuncAttributeMaxDynamicSharedMemorySize, smem_bytes);

    const int grid = (B + ROWS_PER_BLOCK - 1) / ROWS_PER_BLOCK;
    sindy_kernel<<<grid, TPB, smem_bytes>>>(z, out, B);
}

// round 8
// speedup vs baseline: 1.2799x; 1.1746x over previous
#include <cuda_runtime.h>
#include <cuda_bf16.h>
#include <cstdint>

#define D      16
#define LIB    969
#define KPAD   1024
#define TPB    128
#define TILE_M 128
#define NK16   64          // K16 steps over padded K

// Precomputed B fragments (masked coefficients, bf16 hi/lo split), laid out
// exactly as mma.m16n8k16 col-major B fragments: [K16][lane] -> uint4 =
// {b0 nb0, b1 nb0, b0 nb1, b1 nb1}. 64KB each half, L1-resident.
__device__ uint4 g_bfragH[NK16 * 32];
__device__ uint4 g_bfragL[NK16 * 32];

// ---------------- helpers ----------------
__device__ __forceinline__ uint32_t smem_u32(const void* p) {
    uint32_t a;
    asm("{ .reg .u64 t; cvta.to.shared.u64 t, %1; cvt.u32.u64 %0, t; }"
        : "=r"(a) : "l"(p));
    return a;
}
#define LDSM4(r0, r1, r2, r3, addr)                                         \
    asm volatile("ldmatrix.sync.aligned.m8n8.x4.shared.b16 {%0,%1,%2,%3}, [%4];" \
                 : "=r"(r0), "=r"(r1), "=r"(r2), "=r"(r3) : "r"(addr))
#define MMA(d, a0, a1, a2, a3, b0, b1)                                      \
    asm volatile("mma.sync.aligned.m16n8k16.row.col.f32.bf16.bf16.f32 "     \
                 "{%0,%1,%2,%3}, {%4,%5,%6,%7}, {%8,%9}, {%0,%1,%2,%3};"    \
                 : "+f"((d)[0]), "+f"((d)[1]), "+f"((d)[2]), "+f"((d)[3])   \
                 : "r"(a0), "r"(a1), "r"(a2), "r"(a3), "r"(b0), "r"(b1))

// ---------------- prep: mask + bf16 split -> B fragments ----------------
__global__ void prep_kernel(const float* __restrict__ coeff,
                            const float* __restrict__ fixedv,
                            const unsigned char* __restrict__ fmask)
{
    int id = blockIdx.x * blockDim.x + threadIdx.x;
    if (id >= NK16 * 64) return;           // (K16, split, lane)
    int K16   = id >> 6;
    int split = (id >> 5) & 1;
    int lane  = id & 31;
    int g = lane >> 2, tig = lane & 3;
    int kks[4] = {2 * tig, 2 * tig + 1, 2 * tig + 8, 2 * tig + 9};
    unsigned short h[8];
#pragma unroll
    for (int nb = 0; nb < 2; nb++) {
        int n = nb * 8 + g;
#pragma unroll
        for (int e = 0; e < 4; e++) {
            int k = K16 * 16 + kks[e];
            float c = 0.f;
            if (k < LIB) { int s = k * D + n; c = fmask[s] ? fixedv[s] : coeff[s]; }
            __nv_bfloat16 hb = __float2bfloat16(c);            // RN
            float hf = __bfloat162float(hb);
            __nv_bfloat16 lb = __float2bfloat16(c - hf);       // residual
            h[nb * 4 + e] = __bfloat16_as_ushort(split ? lb : hb);
        }
    }
    uint4 r;
    r.x = (uint32_t)h[0] | ((uint32_t)h[1] << 16);   // b0 nb0: low=k even, high=k odd
    r.y = (uint32_t)h[2] | ((uint32_t)h[3] << 16);   // b1 nb0
    r.z = (uint32_t)h[4] | ((uint32_t)h[5] << 16);   // b0 nb1
    r.w = (uint32_t)h[6] | ((uint32_t)h[7] << 16);   // b1 nb1
    (split ? g_bfragL : g_bfragH)[K16 * 32 + lane] = r;
}

// ---------------- per-chunk MMA (warp-local: warp reads only its own rows) ----
__device__ __forceinline__ void chunk_mma(int c, uint32_t sTh, uint32_t sTl,
                                          float (&acc)[2][2][4], int lane, int w)
{
    __syncwarp();
#pragma unroll
    for (int ks = 0; ks < 4; ks++) {
        uint4 bh = __ldg(&g_bfragH[(c * 4 + ks) * 32 + lane]);
        uint4 bl = __ldg(&g_bfragL[(c * 4 + ks) * 32 + lane]);
#pragma unroll
        for (int ms = 0; ms < 2; ms++) {
            int rl   = w * 32 + ms * 16 + (lane & 15);
            int slot = 2 * ks + (lane >> 4);
            uint32_t off = (uint32_t)(rl * 128 + ((slot ^ (rl & 7)) << 4));
            uint32_t a0, a1, a2, a3, l0, l1, l2, l3;
            LDSM4(a0, a1, a2, a3, sTh + off);
            LDSM4(l0, l1, l2, l3, sTl + off);
            MMA(acc[ms][0], a0, a1, a2, a3, bh.x, bh.y);  // Th*Ch nb0
            MMA(acc[ms][1], a0, a1, a2, a3, bh.z, bh.w);  // Th*Ch nb1
            MMA(acc[ms][0], l0, l1, l2, l3, bh.x, bh.y);  // Tl*Ch
            MMA(acc[ms][1], l0, l1, l2, l3, bh.z, bh.w);
            MMA(acc[ms][0], a0, a1, a2, a3, bl.x, bl.y);  // Th*Cl
            MMA(acc[ms][1], a0, a1, a2, a3, bl.z, bl.w);
        }
    }
    __syncwarp();
}

// ---------------- main kernel ----------------
__global__ __launch_bounds__(TPB, 5) void sindy_kernel(
    const float* __restrict__ z,
    float* __restrict__ out,
    int B)
{
    __shared__ __align__(128) unsigned char sTheta[2 * 16384];  // hi | lo chunk tiles
    const uint32_t sTh = smem_u32(sTheta);
    const uint32_t sTl = sTh + 16384;

    const int tid  = threadIdx.x;
    const int lane = tid & 31;
    const int w    = tid >> 5;
    const uint32_t rowoff = (uint32_t)tid * 128;
    const int swz = tid & 7;

    const long row_g = (long)blockIdx.x * TILE_M + tid;
    const bool valid = row_g < B;

    float zv[D];
    {
        const float4* p = (const float4*)(z + row_g * D);
#pragma unroll
        for (int q = 0; q < 4; q++) {
            float4 t4 = valid ? p[q] : make_float4(0.f, 0.f, 0.f, 0.f);
            zv[4*q+0] = t4.x; zv[4*q+1] = t4.y; zv[4*q+2] = t4.z; zv[4*q+3] = t4.w;
        }
    }

    float acc[2][2][4];
#pragma unroll
    for (int a = 0; a < 2; a++)
#pragma unroll
        for (int b = 0; b < 2; b++)
#pragma unroll
            for (int e = 0; e < 4; e++) acc[a][b][e] = 0.f;

    float pend = 0.f;
    uint32_t hbuf[4], lbuf[4];
    int t = 0;   // compile-time folded (everything below fully unrolled)

#define EMIT(expr) do {                                                          \
        float m_ = (expr);                                                       \
        if ((t & 1) == 0) pend = m_;                                             \
        else {                                                                   \
            uint32_t hp_;                                                        \
            asm("cvt.rn.bf16x2.f32 %0, %1, %2;" : "=r"(hp_) : "f"(m_), "f"(pend)); \
            float e0_ = __uint_as_float(hp_ << 16);                              \
            float e1_ = __uint_as_float(hp_ & 0xFFFF0000u);                      \
            float l0_ = pend - e0_;                                              \
            float l1_ = m_   - e1_;                                              \
            uint32_t lp_;                                                        \
            asm("cvt.rn.bf16x2.f32 %0, %1, %2;" : "=r"(lp_) : "f"(l1_), "f"(l0_)); \
            hbuf[(t >> 1) & 3] = hp_;                                            \
            lbuf[(t >> 1) & 3] = lp_;                                            \
            if ((t & 7) == 7) {                                                  \
                int s_ = (t >> 3) & 7;                                           \
                uint32_t off_ = rowoff + (uint32_t)((s_ ^ swz) << 4);            \
                asm volatile("st.shared.v4.b32 [%0], {%1,%2,%3,%4};"             \
                    :: "r"(sTh + off_), "r"(hbuf[0]), "r"(hbuf[1]),              \
                       "r"(hbuf[2]), "r"(hbuf[3]) : "memory");                   \
                asm volatile("st.shared.v4.b32 [%0], {%1,%2,%3,%4};"             \
                    :: "r"(sTl + off_), "r"(lbuf[0]), "r"(lbuf[1]),              \
                       "r"(lbuf[2]), "r"(lbuf[3]) : "memory");                   \
            }                                                                    \
            if ((t & 63) == 63) chunk_mma(t >> 6, sTh, sTl, acc, lane, w);       \
        }                                                                        \
        t++;                                                                     \
    } while (0)

    EMIT(1.0f);                                      // constant term
#pragma unroll
    for (int i = 0; i < D; i++) EMIT(zv[i]);         // order 1
#pragma unroll
    for (int i = 0; i < D; i++)                      // order 2 (i<=j)
#pragma unroll
        for (int j = i; j < D; j++) EMIT(zv[i] * zv[j]);
#pragma unroll
    for (int i = 0; i < D; i++)                      // order 3 (i<=j<=k)
#pragma unroll
        for (int j = i; j < D; j++) {
            float pp = zv[i] * zv[j];
#pragma unroll
            for (int k = j; k < D; k++) EMIT(pp * zv[k]);
        }
#pragma unroll
    for (int pad = LIB; pad < KPAD; pad++) EMIT(0.0f);   // zero padding
#undef EMIT

    // Epilogue: D fragments -> out. lane: g = lane>>2 (row), tig = lane&3 (col pair)
    const int g = lane >> 2, tig = lane & 3;
    const long rbase = (long)blockIdx.x * TILE_M + w * 32;
#pragma unroll
    for (int ms = 0; ms < 2; ms++)
#pragma unroll
        for (int nb = 0; nb < 2; nb++) {
            long r0 = rbase + ms * 16 + g;
            long r1 = r0 + 8;
            int  cn = nb * 8 + 2 * tig;
            if (r0 < B)
                *(float2*)(out + r0 * D + cn) =
                    make_float2(acc[ms][nb][0], acc[ms][nb][1]);
            if (r1 < B)
                *(float2*)(out + r1 * D + cn) =
                    make_float2(acc[ms][nb][2], acc[ms][nb][3]);
        }
}

extern "C" void kernel_launch(void* const* d_in, const int* in_sizes, int n_in,
                              void* d_out, int out_size)
{
    const float*         zin    = (const float*)d_in[0];
    const float*         coeff  = (const float*)d_in[1];
    const float*         fixedv = (const float*)d_in[2];
    const unsigned char* fmask  = (const unsigned char*)d_in[3];
    float*               out    = (float*)d_out;

    const int B = in_sizes[0] / D;

    prep_kernel<<<(NK16 * 64 + 255) / 256, 256>>>(coeff, fixedv, fmask);

    const int grid = (B + TILE_M - 1) / TILE_M;
    sindy_kernel<<<grid, TPB>>>(zin, out, B);
}

// round 9
// speedup vs baseline: 2.1911x; 1.7119x over previous
#include <cuda_runtime.h>
#include <cuda_bf16.h>
#include <cstdint>

#define D      16
#define LIB    969
#define KPAD   1024
#define TPB    128
#define TILE_M 128
#define NK16   64          // K16 steps over padded K

// Precomputed B fragments (masked coefficients, bf16 hi/lo split), laid out
// exactly as mma.m16n8k16 col-major B fragments: [K16][lane] -> uint4 =
// {b0 nb0, b1 nb0, b0 nb1, b1 nb1}.
__device__ uint4 g_bfragH[NK16 * 32];
__device__ uint4 g_bfragL[NK16 * 32];

// ---------------- helpers ----------------
__device__ __forceinline__ uint32_t smem_u32(const void* p) {
    uint32_t a;
    asm("{ .reg .u64 t; cvta.to.shared.u64 t, %1; cvt.u32.u64 %0, t; }"
        : "=r"(a) : "l"(p));
    return a;
}
#define LDSM4(r0, r1, r2, r3, addr)                                         \
    asm volatile("ldmatrix.sync.aligned.m8n8.x4.shared.b16 {%0,%1,%2,%3}, [%4];" \
                 : "=r"(r0), "=r"(r1), "=r"(r2), "=r"(r3) : "r"(addr))
#define MMA(d, a0, a1, a2, a3, b0, b1)                                      \
    asm volatile("mma.sync.aligned.m16n8k16.row.col.f32.bf16.bf16.f32 "     \
                 "{%0,%1,%2,%3}, {%4,%5,%6,%7}, {%8,%9}, {%0,%1,%2,%3};"    \
                 : "+f"((d)[0]), "+f"((d)[1]), "+f"((d)[2]), "+f"((d)[3])   \
                 : "r"(a0), "r"(a1), "r"(a2), "r"(a3), "r"(b0), "r"(b1))

// ---------------- prep: mask + bf16 split -> B fragments ----------------
__global__ void prep_kernel(const float* __restrict__ coeff,
                            const float* __restrict__ fixedv,
                            const unsigned char* __restrict__ fmask)
{
    int id = blockIdx.x * blockDim.x + threadIdx.x;
    if (id >= NK16 * 64) return;           // (K16, split, lane)
    int K16   = id >> 6;
    int split = (id >> 5) & 1;
    int lane  = id & 31;
    int g = lane >> 2, tig = lane & 3;
    int kks[4] = {2 * tig, 2 * tig + 1, 2 * tig + 8, 2 * tig + 9};
    unsigned short h[8];
#pragma unroll
    for (int nb = 0; nb < 2; nb++) {
        int n = nb * 8 + g;
#pragma unroll
        for (int e = 0; e < 4; e++) {
            int k = K16 * 16 + kks[e];
            float c = 0.f;
            if (k < LIB) { int s = k * D + n; c = fmask[s] ? fixedv[s] : coeff[s]; }
            __nv_bfloat16 hb = __float2bfloat16(c);            // RN
            float hf = __bfloat162float(hb);
            __nv_bfloat16 lb = __float2bfloat16(c - hf);       // residual
            h[nb * 4 + e] = __bfloat16_as_ushort(split ? lb : hb);
        }
    }
    uint4 r;
    r.x = (uint32_t)h[0] | ((uint32_t)h[1] << 16);
    r.y = (uint32_t)h[2] | ((uint32_t)h[3] << 16);
    r.z = (uint32_t)h[4] | ((uint32_t)h[5] << 16);
    r.w = (uint32_t)h[6] | ((uint32_t)h[7] << 16);
    (split ? g_bfragL : g_bfragH)[K16 * 32 + lane] = r;
}

// ---------------- per-chunk MMA (warp-local: warp reads only its own rows) ----
__device__ __forceinline__ void chunk_mma(int c, uint32_t sTh, uint32_t sTl,
                                          float (&acc)[2][2][4], int lane, int w)
{
    __syncwarp();
#pragma unroll
    for (int ks = 0; ks < 4; ks++) {
        uint4 bh = __ldg(&g_bfragH[(c * 4 + ks) * 32 + lane]);
        uint4 bl = __ldg(&g_bfragL[(c * 4 + ks) * 32 + lane]);
#pragma unroll
        for (int ms = 0; ms < 2; ms++) {
            int rl   = w * 32 + ms * 16 + (lane & 15);
            int slot = 2 * ks + (lane >> 4);
            uint32_t off = (uint32_t)(rl * 128 + ((slot ^ (rl & 7)) << 4));
            uint32_t a0, a1, a2, a3, l0, l1, l2, l3;
            LDSM4(a0, a1, a2, a3, sTh + off);
            LDSM4(l0, l1, l2, l3, sTl + off);
            MMA(acc[ms][0], a0, a1, a2, a3, bh.x, bh.y);  // Th*Ch nb0
            MMA(acc[ms][1], a0, a1, a2, a3, bh.z, bh.w);  // Th*Ch nb1
            MMA(acc[ms][0], l0, l1, l2, l3, bh.x, bh.y);  // Tl*Ch
            MMA(acc[ms][1], l0, l1, l2, l3, bh.z, bh.w);
            MMA(acc[ms][0], a0, a1, a2, a3, bl.x, bl.y);  // Th*Cl
            MMA(acc[ms][1], a0, a1, a2, a3, bl.z, bl.w);
        }
    }
    __syncwarp();
}

// ---------------- main kernel ----------------
// launch_bounds occupancy 3 (not 5): reg ceiling 170 so the unrolled monomial
// generator does NOT spill to local memory (R8's 96-reg cap caused 240MB of
// spill traffic -> DRAM 20%, issue 29%).
__global__ __launch_bounds__(TPB, 3) void sindy_kernel(
    const float* __restrict__ z,
    float* __restrict__ out,
    int B)
{
    __shared__ __align__(128) unsigned char sTheta[2 * 16384];  // hi | lo chunk tiles
    const uint32_t sTh = smem_u32(sTheta);
    const uint32_t sTl = sTh + 16384;

    const int tid  = threadIdx.x;
    const int lane = tid & 31;
    const int w    = tid >> 5;
    const uint32_t rowoff = (uint32_t)tid * 128;
    const int swz = tid & 7;

    const long row_g = (long)blockIdx.x * TILE_M + tid;
    const bool valid = row_g < B;

    float zv[D];
    {
        const float4* p = (const float4*)(z + row_g * D);
#pragma unroll
        for (int q = 0; q < 4; q++) {
            float4 t4 = valid ? p[q] : make_float4(0.f, 0.f, 0.f, 0.f);
            zv[4*q+0] = t4.x; zv[4*q+1] = t4.y; zv[4*q+2] = t4.z; zv[4*q+3] = t4.w;
        }
    }

    float acc[2][2][4];
#pragma unroll
    for (int a = 0; a < 2; a++)
#pragma unroll
        for (int b = 0; b < 2; b++)
#pragma unroll
            for (int e = 0; e < 4; e++) acc[a][b][e] = 0.f;

    float pend = 0.f;
    uint32_t hbuf[4], lbuf[4];
    int t = 0;   // compile-time folded (everything below fully unrolled)

#define EMIT(expr) do {                                                          \
        float m_ = (expr);                                                       \
        if ((t & 1) == 0) pend = m_;                                             \
        else {                                                                   \
            uint32_t hp_;                                                        \
            asm("cvt.rn.bf16x2.f32 %0, %1, %2;" : "=r"(hp_) : "f"(m_), "f"(pend)); \
            float e0_ = __uint_as_float(hp_ << 16);                              \
            float e1_ = __uint_as_float(hp_ & 0xFFFF0000u);                      \
            float l0_ = pend - e0_;                                              \
            float l1_ = m_   - e1_;                                              \
            uint32_t lp_;                                                        \
            asm("cvt.rn.bf16x2.f32 %0, %1, %2;" : "=r"(lp_) : "f"(l1_), "f"(l0_)); \
            hbuf[(t >> 1) & 3] = hp_;                                            \
            lbuf[(t >> 1) & 3] = lp_;                                            \
            if ((t & 7) == 7) {                                                  \
                int s_ = (t >> 3) & 7;                                           \
                uint32_t off_ = rowoff + (uint32_t)((s_ ^ swz) << 4);            \
                asm volatile("st.shared.v4.b32 [%0], {%1,%2,%3,%4};"             \
                    :: "r"(sTh + off_), "r"(hbuf[0]), "r"(hbuf[1]),              \
                       "r"(hbuf[2]), "r"(hbuf[3]) : "memory");                   \
                asm volatile("st.shared.v4.b32 [%0], {%1,%2,%3,%4};"             \
                    :: "r"(sTl + off_), "r"(lbuf[0]), "r"(lbuf[1]),              \
                       "r"(lbuf[2]), "r"(lbuf[3]) : "memory");                   \
            }                                                                    \
            if ((t & 63) == 63) chunk_mma(t >> 6, sTh, sTl, acc, lane, w);       \
        }                                                                        \
        t++;                                                                     \
    } while (0)

    EMIT(1.0f);                                      // constant term
#pragma unroll
    for (int i = 0; i < D; i++) EMIT(zv[i]);         // order 1
#pragma unroll
    for (int i = 0; i < D; i++)                      // order 2 (i<=j)
#pragma unroll
        for (int j = i; j < D; j++) EMIT(zv[i] * zv[j]);
#pragma unroll
    for (int i = 0; i < D; i++)                      // order 3 (i<=j<=k)
#pragma unroll
        for (int j = i; j < D; j++) {
            float pp = zv[i] * zv[j];
#pragma unroll
            for (int k = j; k < D; k++) EMIT(pp * zv[k]);
        }
#pragma unroll
    for (int pad = LIB; pad < KPAD; pad++) EMIT(0.0f);   // zero padding
#undef EMIT

    // Epilogue: D fragments -> out
    const int g = lane >> 2, tig = lane & 3;
    const long rbase = (long)blockIdx.x * TILE_M + w * 32;
#pragma unroll
    for (int ms = 0; ms < 2; ms++)
#pragma unroll
        for (int nb = 0; nb < 2; nb++) {
            long r0 = rbase + ms * 16 + g;
            long r1 = r0 + 8;
            int  cn = nb * 8 + 2 * tig;
            if (r0 < B)
                *(float2*)(out + r0 * D + cn) =
                    make_float2(acc[ms][nb][0], acc[ms][nb][1]);
            if (r1 < B)
                *(float2*)(out + r1 * D + cn) =
                    make_float2(acc[ms][nb][2], acc[ms][nb][3]);
        }
}

extern "C" void kernel_launch(void* const* d_in, const int* in_sizes, int n_in,
                              void* d_out, int out_size)
{
    const float*         zin    = (const float*)d_in[0];
    const float*         coeff  = (const float*)d_in[1];
    const float*         fixedv = (const float*)d_in[2];
    const unsigned char* fmask  = (const unsigned char*)d_in[3];
    float*               out    = (float*)d_out;

    const int B = in_sizes[0] / D;

    prep_kernel<<<(NK16 * 64 + 255) / 256, 256>>>(coeff, fixedv, fmask);

    const int grid = (B + TILE_M - 1) / TILE_M;
    sindy_kernel<<<grid, TPB>>>(zin, out, B);
}